// round 8
// baseline (speedup 1.0000x reference)
#include <cuda_runtime.h>
#include <cuda_bf16.h>
#include <cstdint>

typedef unsigned long long ull;

#define MAXT 66560
#define MAXB 2048

// Scratch (static device allocations — no cudaMalloc allowed)
__device__ float         g_qkv[(size_t)MAXT * 384];
__device__ __nv_bfloat16 g_ah[(size_t)MAXT * 128];
__device__ __nv_bfloat16 g_al[(size_t)MAXT * 128];
__device__ __nv_bfloat16 g_oh[(size_t)MAXT * 128];
__device__ __nv_bfloat16 g_ol[(size_t)MAXT * 128];
__device__ __nv_bfloat16 g_wh1[384 * 128];
__device__ __nv_bfloat16 g_wl1[384 * 128];
__device__ __nv_bfloat16 g_wh2[128 * 128];
__device__ __nv_bfloat16 g_wl2[128 * 128];
__device__ int           g_offs[MAXB];

// ---------------------------------------------------------------------------
// f32x2 helpers (attention kernel)
// ---------------------------------------------------------------------------
__device__ __forceinline__ ull pack2(float lo, float hi) {
    ull r;
    asm("mov.b64 %0, {%1, %2};" : "=l"(r)
        : "r"(__float_as_uint(lo)), "r"(__float_as_uint(hi)));
    return r;
}
__device__ __forceinline__ ull ffma2(ull a, ull b, ull c) {
    ull d;
    asm("fma.rn.f32x2 %0, %1, %2, %3;" : "=l"(d) : "l"(a), "l"(b), "l"(c));
    return d;
}
__device__ __forceinline__ ull mul2(ull a, ull b) {
    ull d;
    asm("mul.rn.f32x2 %0, %1, %2;" : "=l"(d) : "l"(a), "l"(b));
    return d;
}
__device__ __forceinline__ ull add2(ull a, ull b) {
    ull d;
    asm("add.rn.f32x2 %0, %1, %2;" : "=l"(d) : "l"(a), "l"(b));
    return d;
}
__device__ __forceinline__ float lo2(ull v) { return __uint_as_float((unsigned)(v & 0xffffffffull)); }
__device__ __forceinline__ float hi2(ull v) { return __uint_as_float((unsigned)(v >> 32)); }
__device__ __forceinline__ float hadd2(ull v) { return lo2(v) + hi2(v); }

__device__ __forceinline__ uint32_t smem_u32(const void* p) {
    uint32_t a;
    asm("{ .reg .u64 t; cvta.to.shared.u64 t, %1; cvt.u32.u64 %0, t; }" : "=r"(a) : "l"(p));
    return a;
}
__device__ __forceinline__ void cp16(uint32_t s, const void* g) {
    asm volatile("cp.async.ca.shared.global [%0], [%1], 16;" :: "r"(s), "l"(g));
}
#define CP_COMMIT() asm volatile("cp.async.commit_group;" ::: "memory")
#define CP_WAIT()   asm volatile("cp.async.wait_group 0;" ::: "memory")

// ---------------------------------------------------------------------------
// Conversion kernel: fp32 -> bf16 hi + bf16 lo planes (4 elems/thread)
// ---------------------------------------------------------------------------
__global__ void conv_kernel(const float* __restrict__ src,
                            __nv_bfloat16* __restrict__ dh,
                            __nv_bfloat16* __restrict__ dl, int n4)
{
    int i = blockIdx.x * blockDim.x + threadIdx.x;
    if (i >= n4) return;
    float4 v = ((const float4*)src)[i];
    __nv_bfloat16 hx = __float2bfloat16(v.x), hy = __float2bfloat16(v.y),
                  hz = __float2bfloat16(v.z), hw = __float2bfloat16(v.w);
    ull hp = (ull)__bfloat16_as_ushort(hx) | ((ull)__bfloat16_as_ushort(hy) << 16)
           | ((ull)__bfloat16_as_ushort(hz) << 32) | ((ull)__bfloat16_as_ushort(hw) << 48);
    __nv_bfloat16 lx = __float2bfloat16(v.x - __bfloat162float(hx));
    __nv_bfloat16 ly = __float2bfloat16(v.y - __bfloat162float(hy));
    __nv_bfloat16 lz = __float2bfloat16(v.z - __bfloat162float(hz));
    __nv_bfloat16 lw = __float2bfloat16(v.w - __bfloat162float(hw));
    ull lp = (ull)__bfloat16_as_ushort(lx) | ((ull)__bfloat16_as_ushort(ly) << 16)
           | ((ull)__bfloat16_as_ushort(lz) << 32) | ((ull)__bfloat16_as_ushort(lw) << 48);
    *(ull*)(dh + (size_t)i * 4) = hp;
    *(ull*)(dl + (size_t)i * 4) = lp;
}

// ---------------------------------------------------------------------------
// Kernel: exclusive prefix sum of agents_per_sample -> g_offs
// ---------------------------------------------------------------------------
__global__ void scan_kernel(const int* __restrict__ agents, int B) {
    __shared__ int part[256];
    int tid = threadIdx.x;
    int local[8];
    int s = 0;
#pragma unroll
    for (int i = 0; i < 8; i++) {
        int idx = tid * 8 + i;
        local[i] = (idx < B) ? agents[idx] : 0;
        s += local[i];
    }
    part[tid] = s;
    __syncthreads();
    for (int d = 1; d < 256; d <<= 1) {
        int v = (tid >= d) ? part[tid - d] : 0;
        __syncthreads();
        part[tid] += v;
        __syncthreads();
    }
    int base = (tid > 0) ? part[tid - 1] : 0;
#pragma unroll
    for (int i = 0; i < 8; i++) {
        int idx = tid * 8 + i;
        if (idx < B) g_offs[idx] = base;
        base += local[i];
    }
}

// ---------------------------------------------------------------------------
// GEMM v5 (warp HMMA, pre-converted bf16 planes): 64x128 CTA tile, K=128.
// cp.async fill (no conversion), 2 CTAs/SM. 3-term: Ah*Wh + Ah*Wl + Al*Wh.
// ---------------------------------------------------------------------------
#define ASTRIDE 136                  // bf16 elems per smem row (272B)
#define SA_H 0
#define SA_L 17408                   // 64*136*2
#define SW_H 34816
#define SW_L 69632                   // + 128*136*2
#define GEMM_SMEM 104448

__device__ __forceinline__ void ldm_x4(uint32_t* r, uint32_t addr) {
    asm volatile("ldmatrix.sync.aligned.m8n8.x4.shared.b16 {%0,%1,%2,%3}, [%4];"
                 : "=r"(r[0]), "=r"(r[1]), "=r"(r[2]), "=r"(r[3]) : "r"(addr));
}
__device__ __forceinline__ void mma_bf16(float* d, const uint32_t* a, const uint32_t* b) {
    asm volatile("mma.sync.aligned.m16n8k16.row.col.f32.bf16.bf16.f32 "
                 "{%0,%1,%2,%3}, {%4,%5,%6,%7}, {%8,%9}, {%0,%1,%2,%3};"
                 : "+f"(d[0]), "+f"(d[1]), "+f"(d[2]), "+f"(d[3])
                 : "r"(a[0]), "r"(a[1]), "r"(a[2]), "r"(a[3]), "r"(b[0]), "r"(b[1]));
}

__global__ __launch_bounds__(256, 2) void gemm_tc_kernel(
    const __nv_bfloat16* __restrict__ Ah, const __nv_bfloat16* __restrict__ Al,
    const __nv_bfloat16* __restrict__ Wh, const __nv_bfloat16* __restrict__ Wl,
    const float* __restrict__ bias, float* __restrict__ C, int N)
{
    extern __shared__ char sm[];
    const uint32_t sb = smem_u32(sm);
    const int tid  = threadIdx.x;
    const int wid  = tid >> 5;
    const int lane = tid & 31;
    const int bm   = blockIdx.x * 64;
    const int bn   = blockIdx.y * 128;

    // ---- cp.async fill: A planes (64 rows) + W planes (128 rows) ----
#pragma unroll
    for (int t = 0; t < 4; t++) {
        int c = tid + t * 256;           // 0..1023
        int row = c >> 4, c16 = c & 15;
        uint32_t so = (uint32_t)(row * 272 + c16 * 16);
        const char* gh = (const char*)(Ah + (size_t)(bm + row) * 128) + c16 * 16;
        const char* gl = (const char*)(Al + (size_t)(bm + row) * 128) + c16 * 16;
        cp16(sb + SA_H + so, gh);
        cp16(sb + SA_L + so, gl);
    }
#pragma unroll
    for (int t = 0; t < 8; t++) {
        int c = tid + t * 256;           // 0..2047
        int row = c >> 4, c16 = c & 15;
        uint32_t so = (uint32_t)(row * 272 + c16 * 16);
        const char* gh = (const char*)(Wh + (size_t)(bn + row) * 128) + c16 * 16;
        const char* gl = (const char*)(Wl + (size_t)(bn + row) * 128) + c16 * 16;
        cp16(sb + SW_H + so, gh);
        cp16(sb + SW_L + so, gl);
    }
    CP_COMMIT();
    CP_WAIT();
    __syncthreads();

    // ---- mainloop: 8 warps in 2(m) x 4(n); warp region 32x32 ----
    const int wm = (wid & 1) * 32;
    const int wn = (wid >> 1) * 32;

    float acc[2][4][4];
#pragma unroll
    for (int mi = 0; mi < 2; mi++)
#pragma unroll
        for (int ni = 0; ni < 4; ni++)
#pragma unroll
            for (int e = 0; e < 4; e++) acc[mi][ni][e] = 0.f;

    const int arow = wm + (lane & 15);
    const int brow = wn + (lane >> 2);
    const int bcol = (lane & 3) * 2;

#pragma unroll
    for (int k = 0; k < 8; k++) {
        const int kb = k * 16;
        uint32_t ahf[2][4], alf[2][4];
#pragma unroll
        for (int mi = 0; mi < 2; mi++) {
            uint32_t off = (uint32_t)(((arow + mi * 16) * ASTRIDE + kb + (lane >> 4) * 8) * 2);
            ldm_x4(ahf[mi], sb + SA_H + off);
            ldm_x4(alf[mi], sb + SA_L + off);
        }
        uint32_t bhf[4][2], blf[4][2];
#pragma unroll
        for (int ni = 0; ni < 4; ni++) {
            uint32_t off0 = (uint32_t)(((brow + ni * 8) * ASTRIDE + kb + bcol) * 2);
            bhf[ni][0] = *(const uint32_t*)(sm + SW_H + off0);
            bhf[ni][1] = *(const uint32_t*)(sm + SW_H + off0 + 16);
            blf[ni][0] = *(const uint32_t*)(sm + SW_L + off0);
            blf[ni][1] = *(const uint32_t*)(sm + SW_L + off0 + 16);
        }
#pragma unroll
        for (int mi = 0; mi < 2; mi++)
#pragma unroll
            for (int ni = 0; ni < 4; ni++) {
                mma_bf16(acc[mi][ni], ahf[mi], bhf[ni]);
                mma_bf16(acc[mi][ni], ahf[mi], blf[ni]);
                mma_bf16(acc[mi][ni], alf[mi], bhf[ni]);
            }
    }

    // ---- epilogue: bias + store ----
    const int er = lane >> 2;
    const int ec = (lane & 3) * 2;
#pragma unroll
    for (int ni = 0; ni < 4; ni++) {
        int n = bn + wn + ni * 8 + ec;
        float b0 = bias[n], b1 = bias[n + 1];
#pragma unroll
        for (int mi = 0; mi < 2; mi++) {
            int m0 = bm + wm + mi * 16 + er;
            *(float2*)(C + (size_t)m0 * N + n) =
                make_float2(acc[mi][ni][0] + b0, acc[mi][ni][1] + b1);
            *(float2*)(C + (size_t)(m0 + 8) * N + n) =
                make_float2(acc[mi][ni][2] + b0, acc[mi][ni][3] + b1);
        }
    }
}

// ---------------------------------------------------------------------------
// Attention v3: warp per (sample, head). Writes bf16 hi/lo output planes
// (fuses out_proj input conversion). Uniform fast path for n <= 32.
// ---------------------------------------------------------------------------
__device__ __forceinline__ void store_bf_split(
    __nv_bfloat16* __restrict__ Oh, __nv_bfloat16* __restrict__ Ol,
    size_t base, const ull* ov, float linv)
{
    ull inv = pack2(linv, linv);
#pragma unroll
    for (int t = 0; t < 4; t++) {
        ull r0 = mul2(ov[2 * t], inv);
        ull r1 = mul2(ov[2 * t + 1], inv);
        float f0 = lo2(r0), f1 = hi2(r0), f2 = lo2(r1), f3 = hi2(r1);
        __nv_bfloat16 h0 = __float2bfloat16(f0), h1 = __float2bfloat16(f1),
                      h2 = __float2bfloat16(f2), h3 = __float2bfloat16(f3);
        ull hp = (ull)__bfloat16_as_ushort(h0) | ((ull)__bfloat16_as_ushort(h1) << 16)
               | ((ull)__bfloat16_as_ushort(h2) << 32) | ((ull)__bfloat16_as_ushort(h3) << 48);
        __nv_bfloat16 l0 = __float2bfloat16(f0 - __bfloat162float(h0));
        __nv_bfloat16 l1 = __float2bfloat16(f1 - __bfloat162float(h1));
        __nv_bfloat16 l2 = __float2bfloat16(f2 - __bfloat162float(h2));
        __nv_bfloat16 l3 = __float2bfloat16(f3 - __bfloat162float(h3));
        ull lp = (ull)__bfloat16_as_ushort(l0) | ((ull)__bfloat16_as_ushort(l1) << 16)
               | ((ull)__bfloat16_as_ushort(l2) << 32) | ((ull)__bfloat16_as_ushort(l3) << 48);
        *(ull*)(Oh + base + t * 4) = hp;
        *(ull*)(Ol + base + t * 4) = lp;
    }
}

__global__ __launch_bounds__(256) void attn_kernel(
    const float* __restrict__ Y,            // qkv [T][384]
    __nv_bfloat16* __restrict__ Oh,         // attn out hi plane [T][128]
    __nv_bfloat16* __restrict__ Ol,         // attn out lo plane [T][128]
    const int* __restrict__ agents)
{
    extern __shared__ float smf[];       // 8 warps * (1024 K + 1024 V) floats
    const int b    = blockIdx.x;
    const int tid  = threadIdx.x;
    const int w    = tid >> 5;           // head index
    const int lane = tid & 31;
    const int n    = agents[b];
    const int o    = g_offs[b];

    float* Ks = smf + w * 2048;
    float* Vs = Ks + 1024;

    int nseg = n * 4;
    for (int si = lane; si < nseg; si += 32) {
        int r = si >> 2, s = si & 3;
        const float* base = Y + (size_t)(o + r) * 384 + w * 16 + s * 4;
        *(float4*)(Ks + r * 16 + s * 4) = *(const float4*)(base + 128);
        *(float4*)(Vs + r * 16 + s * 4) = *(const float4*)(base + 256);
    }

    const int i0 = lane, i1 = lane + 32;
    const ull QSC = pack2(0.25f, 0.25f);

    ull q0[8];
#pragma unroll
    for (int d = 0; d < 8; d++) q0[d] = 0ull;
    if (i0 < n) {
        const float4* qp = (const float4*)(Y + (size_t)(o + i0) * 384 + w * 16);
#pragma unroll
        for (int t = 0; t < 4; t++) {
            float4 v = qp[t];
            q0[t * 2 + 0] = mul2(pack2(v.x, v.y), QSC);
            q0[t * 2 + 1] = mul2(pack2(v.z, v.w), QSC);
        }
    }

    if (n > 32) {
        // ---- two-query path ----
        ull q1[8];
#pragma unroll
        for (int d = 0; d < 8; d++) q1[d] = 0ull;
        if (i1 < n) {
            const float4* qp = (const float4*)(Y + (size_t)(o + i1) * 384 + w * 16);
#pragma unroll
            for (int t = 0; t < 4; t++) {
                float4 v = qp[t];
                q1[t * 2 + 0] = mul2(pack2(v.x, v.y), QSC);
                q1[t * 2 + 1] = mul2(pack2(v.z, v.w), QSC);
            }
        }
        __syncwarp();

        ull o0[8], o1[8];
#pragma unroll
        for (int d = 0; d < 8; d++) { o0[d] = 0ull; o1[d] = 0ull; }
        float l0 = 0.f, l1 = 0.f;

#pragma unroll 2
        for (int j = 0; j < n; j++) {
            const ulonglong2* kp = (const ulonglong2*)(Ks + j * 16);
            ulonglong2 k01 = kp[0], k23 = kp[1], k45 = kp[2], k67 = kp[3];
            ull kv[8] = {k01.x, k01.y, k23.x, k23.y, k45.x, k45.y, k67.x, k67.y};

            ull saA = 0, saB = 0, sbA = 0, sbB = 0;
#pragma unroll
            for (int d = 0; d < 4; d++) {
                saA = ffma2(q0[2 * d], kv[2 * d], saA);
                saB = ffma2(q0[2 * d + 1], kv[2 * d + 1], saB);
                sbA = ffma2(q1[2 * d], kv[2 * d], sbA);
                sbB = ffma2(q1[2 * d + 1], kv[2 * d + 1], sbB);
            }
            float e0 = __expf(hadd2(add2(saA, saB)));
            float e1 = __expf(hadd2(add2(sbA, sbB)));
            l0 += e0;
            l1 += e1;
            ull e00 = pack2(e0, e0);
            ull e11 = pack2(e1, e1);

            const ulonglong2* vp = (const ulonglong2*)(Vs + j * 16);
            ulonglong2 v01 = vp[0], v23 = vp[1], v45 = vp[2], v67 = vp[3];
            ull vv[8] = {v01.x, v01.y, v23.x, v23.y, v45.x, v45.y, v67.x, v67.y};
#pragma unroll
            for (int d = 0; d < 8; d++) {
                o0[d] = ffma2(e00, vv[d], o0[d]);
                o1[d] = ffma2(e11, vv[d], o1[d]);
            }
        }

        if (i0 < n) store_bf_split(Oh, Ol, (size_t)(o + i0) * 128 + w * 16, o0, 1.f / l0);
        if (i1 < n) store_bf_split(Oh, Ol, (size_t)(o + i1) * 128 + w * 16, o1, 1.f / l1);
    } else {
        // ---- single-query path (n <= 32) ----
        __syncwarp();
        ull o0[8];
#pragma unroll
        for (int d = 0; d < 8; d++) o0[d] = 0ull;
        float l0 = 0.f;

#pragma unroll 2
        for (int j = 0; j < n; j++) {
            const ulonglong2* kp = (const ulonglong2*)(Ks + j * 16);
            ulonglong2 k01 = kp[0], k23 = kp[1], k45 = kp[2], k67 = kp[3];
            ull kv[8] = {k01.x, k01.y, k23.x, k23.y, k45.x, k45.y, k67.x, k67.y};

            ull saA = 0, saB = 0;
#pragma unroll
            for (int d = 0; d < 4; d++) {
                saA = ffma2(q0[2 * d], kv[2 * d], saA);
                saB = ffma2(q0[2 * d + 1], kv[2 * d + 1], saB);
            }
            float e0 = __expf(hadd2(add2(saA, saB)));
            l0 += e0;
            ull e00 = pack2(e0, e0);

            const ulonglong2* vp = (const ulonglong2*)(Vs + j * 16);
            ulonglong2 v01 = vp[0], v23 = vp[1], v45 = vp[2], v67 = vp[3];
            ull vv[8] = {v01.x, v01.y, v23.x, v23.y, v45.x, v45.y, v67.x, v67.y};
#pragma unroll
            for (int d = 0; d < 8; d++)
                o0[d] = ffma2(e00, vv[d], o0[d]);
        }

        if (i0 < n) store_bf_split(Oh, Ol, (size_t)(o + i0) * 128 + w * 16, o0, 1.f / l0);
    }
}

// ---------------------------------------------------------------------------
extern "C" void kernel_launch(void* const* d_in, const int* in_sizes, int n_in,
                              void* d_out, int out_size)
{
    const float* att_in = (const float*)d_in[0];
    const float* in_w   = (const float*)d_in[1];
    const float* in_b   = (const float*)d_in[2];
    const float* out_w  = (const float*)d_in[3];
    const float* out_b  = (const float*)d_in[4];
    const int*   agents = (const int*)d_in[5];

    const int T = in_sizes[0] / 128;
    const int B = in_sizes[5];
    float* out  = (float*)d_out;

    float *qkv = nullptr;
    __nv_bfloat16 *ah, *al, *oh, *ol, *wh1, *wl1, *wh2, *wl2;
    cudaGetSymbolAddress((void**)&qkv, g_qkv);
    cudaGetSymbolAddress((void**)&ah,  g_ah);
    cudaGetSymbolAddress((void**)&al,  g_al);
    cudaGetSymbolAddress((void**)&oh,  g_oh);
    cudaGetSymbolAddress((void**)&ol,  g_ol);
    cudaGetSymbolAddress((void**)&wh1, g_wh1);
    cudaGetSymbolAddress((void**)&wl1, g_wl1);
    cudaGetSymbolAddress((void**)&wh2, g_wh2);
    cudaGetSymbolAddress((void**)&wl2, g_wl2);

    cudaFuncSetAttribute(gemm_tc_kernel, cudaFuncAttributeMaxDynamicSharedMemorySize, GEMM_SMEM);
    cudaFuncSetAttribute(attn_kernel, cudaFuncAttributeMaxDynamicSharedMemorySize, 65536);

    // conversions + scan (independent)
    int n4A = T * 32;
    conv_kernel<<<(n4A + 255) / 256, 256>>>(att_in, ah, al, n4A);
    conv_kernel<<<48, 256>>>(in_w, wh1, wl1, 384 * 32);
    conv_kernel<<<16, 256>>>(out_w, wh2, wl2, 128 * 32);
    scan_kernel<<<1, 256>>>(agents, B);

    // QKV GEMM: [T x 384]
    dim3 g1(T / 64, 3);
    gemm_tc_kernel<<<g1, 256, GEMM_SMEM>>>(ah, al, wh1, wl1, in_b, qkv, 384);

    // attention -> bf16 hi/lo planes
    attn_kernel<<<B, 256, 65536>>>(qkv, oh, ol, agents);

    // out_proj GEMM: [T x 128]
    dim3 g2(T / 64, 1);
    gemm_tc_kernel<<<g2, 256, GEMM_SMEM>>>(oh, ol, wh2, wl2, out_b, out, 128);
}

// round 9
// speedup vs baseline: 1.1447x; 1.1447x over previous
#include <cuda_runtime.h>
#include <cuda_bf16.h>
#include <cstdint>

typedef unsigned long long ull;

#define MAXT 66560
#define MAXB 2048

// Scratch (static device allocations — no cudaMalloc allowed)
__device__ float         g_qkv[(size_t)MAXT * 384];
__device__ __nv_bfloat16 g_oh[(size_t)MAXT * 128];
__device__ __nv_bfloat16 g_ol[(size_t)MAXT * 128];
__device__ __nv_bfloat16 g_wh1[384 * 128];
__device__ __nv_bfloat16 g_wl1[384 * 128];
__device__ __nv_bfloat16 g_wh2[128 * 128];
__device__ __nv_bfloat16 g_wl2[128 * 128];
__device__ int           g_offs[MAXB];

// ---------------------------------------------------------------------------
// f32x2 helpers
// ---------------------------------------------------------------------------
__device__ __forceinline__ ull pack2(float lo, float hi) {
    ull r;
    asm("mov.b64 %0, {%1, %2};" : "=l"(r)
        : "r"(__float_as_uint(lo)), "r"(__float_as_uint(hi)));
    return r;
}
__device__ __forceinline__ ull ffma2(ull a, ull b, ull c) {
    ull d;
    asm("fma.rn.f32x2 %0, %1, %2, %3;" : "=l"(d) : "l"(a), "l"(b), "l"(c));
    return d;
}
__device__ __forceinline__ ull mul2(ull a, ull b) {
    ull d;
    asm("mul.rn.f32x2 %0, %1, %2;" : "=l"(d) : "l"(a), "l"(b));
    return d;
}
__device__ __forceinline__ ull add2(ull a, ull b) {
    ull d;
    asm("add.rn.f32x2 %0, %1, %2;" : "=l"(d) : "l"(a), "l"(b));
    return d;
}
__device__ __forceinline__ float lo2(ull v) { return __uint_as_float((unsigned)(v & 0xffffffffull)); }
__device__ __forceinline__ float hi2(ull v) { return __uint_as_float((unsigned)(v >> 32)); }
__device__ __forceinline__ float hadd2(ull v) { return lo2(v) + hi2(v); }

__device__ __forceinline__ uint32_t smem_u32(const void* p) {
    uint32_t a;
    asm("{ .reg .u64 t; cvta.to.shared.u64 t, %1; cvt.u32.u64 %0, t; }" : "=r"(a) : "l"(p));
    return a;
}
__device__ __forceinline__ void cp16(uint32_t s, const void* g) {
    asm volatile("cp.async.ca.shared.global [%0], [%1], 16;" :: "r"(s), "l"(g));
}
#define CP_COMMIT() asm volatile("cp.async.commit_group;" ::: "memory")
#define CP_WAIT()   asm volatile("cp.async.wait_group 0;" ::: "memory")

// ---------------------------------------------------------------------------
// Weight conversion: fp32 -> bf16 hi/lo planes for both weight matrices.
// grid = 64 blocks x 256 thr: blocks 0..47 -> in_w (384x128), 48..63 -> out_w.
// ---------------------------------------------------------------------------
__global__ void convw_kernel(const float* __restrict__ w1,
                             const float* __restrict__ w2)
{
    int bid = blockIdx.x;
    const float* src;
    __nv_bfloat16 *dh, *dl;
    int i;
    if (bid < 48) {
        src = w1; dh = g_wh1; dl = g_wl1;
        i = bid * 256 + threadIdx.x;          // < 12288 float4s
    } else {
        src = w2; dh = g_wh2; dl = g_wl2;
        i = (bid - 48) * 256 + threadIdx.x;   // < 4096 float4s
    }
    float4 v = ((const float4*)src)[i];
    __nv_bfloat16 hx = __float2bfloat16(v.x), hy = __float2bfloat16(v.y),
                  hz = __float2bfloat16(v.z), hw = __float2bfloat16(v.w);
    ull hp = (ull)__bfloat16_as_ushort(hx) | ((ull)__bfloat16_as_ushort(hy) << 16)
           | ((ull)__bfloat16_as_ushort(hz) << 32) | ((ull)__bfloat16_as_ushort(hw) << 48);
    __nv_bfloat16 lx = __float2bfloat16(v.x - __bfloat162float(hx));
    __nv_bfloat16 ly = __float2bfloat16(v.y - __bfloat162float(hy));
    __nv_bfloat16 lz = __float2bfloat16(v.z - __bfloat162float(hz));
    __nv_bfloat16 lw = __float2bfloat16(v.w - __bfloat162float(hw));
    ull lp = (ull)__bfloat16_as_ushort(lx) | ((ull)__bfloat16_as_ushort(ly) << 16)
           | ((ull)__bfloat16_as_ushort(lz) << 32) | ((ull)__bfloat16_as_ushort(lw) << 48);
    *(ull*)(dh + (size_t)i * 4) = hp;
    *(ull*)(dl + (size_t)i * 4) = lp;
}

// ---------------------------------------------------------------------------
// Kernel: exclusive prefix sum of agents_per_sample -> g_offs
// ---------------------------------------------------------------------------
__global__ void scan_kernel(const int* __restrict__ agents, int B) {
    __shared__ int part[256];
    int tid = threadIdx.x;
    int local[8];
    int s = 0;
#pragma unroll
    for (int i = 0; i < 8; i++) {
        int idx = tid * 8 + i;
        local[i] = (idx < B) ? agents[idx] : 0;
        s += local[i];
    }
    part[tid] = s;
    __syncthreads();
    for (int d = 1; d < 256; d <<= 1) {
        int v = (tid >= d) ? part[tid - d] : 0;
        __syncthreads();
        part[tid] += v;
        __syncthreads();
    }
    int base = (tid > 0) ? part[tid - 1] : 0;
#pragma unroll
    for (int i = 0; i < 8; i++) {
        int idx = tid * 8 + i;
        if (idx < B) g_offs[idx] = base;
        base += local[i];
    }
}

// ---------------------------------------------------------------------------
// GEMM v6 (warp HMMA): 64x128 CTA tile, K=128, 2 CTAs/SM.
// CONVERT_A: A read as fp32 and split in-kernel; else A read as bf16 planes.
// W always pre-converted planes via cp.async. B frags via ldmatrix.x4.
// 3-term split: Ah*Wh + Ah*Wl + Al*Wh.
// ---------------------------------------------------------------------------
#define ASTRIDE 136                  // bf16 elems per smem row (272B)
#define SA_H 0
#define SA_L 17408                   // 64*136*2
#define SW_H 34816
#define SW_L 69632
#define GEMM_SMEM 104448

__device__ __forceinline__ void ldm_x4(uint32_t* r, uint32_t addr) {
    asm volatile("ldmatrix.sync.aligned.m8n8.x4.shared.b16 {%0,%1,%2,%3}, [%4];"
                 : "=r"(r[0]), "=r"(r[1]), "=r"(r[2]), "=r"(r[3]) : "r"(addr));
}
__device__ __forceinline__ void mma_bf16(float* d, const uint32_t* a, const uint32_t* b) {
    asm volatile("mma.sync.aligned.m16n8k16.row.col.f32.bf16.bf16.f32 "
                 "{%0,%1,%2,%3}, {%4,%5,%6,%7}, {%8,%9}, {%0,%1,%2,%3};"
                 : "+f"(d[0]), "+f"(d[1]), "+f"(d[2]), "+f"(d[3])
                 : "r"(a[0]), "r"(a[1]), "r"(a[2]), "r"(a[3]), "r"(b[0]), "r"(b[1]));
}

template <bool CONVERT_A>
__global__ __launch_bounds__(256, 2) void gemm_tc_kernel(
    const void* __restrict__ Asrc,                 // fp32 [.][128] or unused
    const __nv_bfloat16* __restrict__ Ah_g, const __nv_bfloat16* __restrict__ Al_g,
    const __nv_bfloat16* __restrict__ Wh, const __nv_bfloat16* __restrict__ Wl,
    const float* __restrict__ bias, float* __restrict__ C, int N)
{
    extern __shared__ char sm[];
    const uint32_t sb = smem_u32(sm);
    const int tid  = threadIdx.x;
    const int wid  = tid >> 5;
    const int lane = tid & 31;
    const int bm   = blockIdx.x * 64;
    const int bn   = blockIdx.y * 128;

    // ---- W planes via cp.async (128 rows) ----
#pragma unroll
    for (int t = 0; t < 8; t++) {
        int c = tid + t * 256;           // 0..2047
        int row = c >> 4, c16 = c & 15;
        uint32_t so = (uint32_t)(row * 272 + c16 * 16);
        cp16(sb + SW_H + so, (const char*)(Wh + (size_t)(bn + row) * 128) + c16 * 16);
        cp16(sb + SW_L + so, (const char*)(Wl + (size_t)(bn + row) * 128) + c16 * 16);
    }

    // ---- A tile (64 rows) ----
    if (CONVERT_A) {
        const float* A = (const float*)Asrc;
#pragma unroll
        for (int it = 0; it < 8; it++) {
            int idx = tid + it * 256;            // 0..2047 float4s
            int row = idx >> 5;
            int col = (idx & 31) * 4;
            int so  = row * ASTRIDE + col;
            float4 v = *(const float4*)(A + (size_t)(bm + row) * 128 + col);
            __nv_bfloat16 hx = __float2bfloat16(v.x), hy = __float2bfloat16(v.y),
                          hz = __float2bfloat16(v.z), hw = __float2bfloat16(v.w);
            ull hp = (ull)__bfloat16_as_ushort(hx) | ((ull)__bfloat16_as_ushort(hy) << 16)
                   | ((ull)__bfloat16_as_ushort(hz) << 32) | ((ull)__bfloat16_as_ushort(hw) << 48);
            __nv_bfloat16 lx = __float2bfloat16(v.x - __bfloat162float(hx));
            __nv_bfloat16 ly = __float2bfloat16(v.y - __bfloat162float(hy));
            __nv_bfloat16 lz = __float2bfloat16(v.z - __bfloat162float(hz));
            __nv_bfloat16 lw = __float2bfloat16(v.w - __bfloat162float(hw));
            ull lp = (ull)__bfloat16_as_ushort(lx) | ((ull)__bfloat16_as_ushort(ly) << 16)
                   | ((ull)__bfloat16_as_ushort(lz) << 32) | ((ull)__bfloat16_as_ushort(lw) << 48);
            *(ull*)(sm + SA_H + so * 2) = hp;
            *(ull*)(sm + SA_L + so * 2) = lp;
        }
    } else {
#pragma unroll
        for (int t = 0; t < 4; t++) {
            int c = tid + t * 256;           // 0..1023
            int row = c >> 4, c16 = c & 15;
            uint32_t so = (uint32_t)(row * 272 + c16 * 16);
            cp16(sb + SA_H + so, (const char*)(Ah_g + (size_t)(bm + row) * 128) + c16 * 16);
            cp16(sb + SA_L + so, (const char*)(Al_g + (size_t)(bm + row) * 128) + c16 * 16);
        }
    }
    CP_COMMIT();
    CP_WAIT();
    __syncthreads();

    // ---- mainloop: 8 warps in 2(m) x 4(n); warp region 32x32 ----
    const int wm = (wid & 1) * 32;
    const int wn = (wid >> 1) * 32;

    float acc[2][4][4];
#pragma unroll
    for (int mi = 0; mi < 2; mi++)
#pragma unroll
        for (int ni = 0; ni < 4; ni++)
#pragma unroll
            for (int e = 0; e < 4; e++) acc[mi][ni][e] = 0.f;

    // A ldmatrix address: row = wm + lane&15 (+16 for mi=1), col byte = (lane>>4)*16
    const int arow = wm + (lane & 15);
    // B ldmatrix address (x4 covers ni pair, both k-halves):
    //   group = lane>>3, r = lane&7
    //   n = wn + nip*16 + (group>>1)*8 + r ; kcol = kb + (group&1)*8
    const int bgrp = lane >> 3;
    const int brow0 = wn + ((bgrp >> 1) << 3) + (lane & 7);
    const int bk8   = (bgrp & 1) << 3;

#pragma unroll
    for (int k = 0; k < 8; k++) {
        const int kb = k * 16;
        uint32_t ahf[2][4], alf[2][4];
#pragma unroll
        for (int mi = 0; mi < 2; mi++) {
            uint32_t off = (uint32_t)(((arow + mi * 16) * ASTRIDE + kb + (lane >> 4) * 8) * 2);
            ldm_x4(ahf[mi], sb + SA_H + off);
            ldm_x4(alf[mi], sb + SA_L + off);
        }
        uint32_t bhf[4][2], blf[4][2];
#pragma unroll
        for (int nip = 0; nip < 2; nip++) {
            uint32_t off = (uint32_t)(((brow0 + nip * 16) * ASTRIDE + kb + bk8) * 2);
            ldm_x4(&bhf[nip * 2][0], sb + SW_H + off);   // {b[ni][0],b[ni][1],b[ni+1][0],b[ni+1][1]}
            ldm_x4(&blf[nip * 2][0], sb + SW_L + off);
        }
#pragma unroll
        for (int mi = 0; mi < 2; mi++)
#pragma unroll
            for (int ni = 0; ni < 4; ni++) {
                mma_bf16(acc[mi][ni], ahf[mi], bhf[ni]);
                mma_bf16(acc[mi][ni], ahf[mi], blf[ni]);
                mma_bf16(acc[mi][ni], alf[mi], bhf[ni]);
            }
    }

    // ---- epilogue: bias + store ----
    const int er = lane >> 2;
    const int ec = (lane & 3) * 2;
#pragma unroll
    for (int ni = 0; ni < 4; ni++) {
        int n = bn + wn + ni * 8 + ec;
        float b0 = bias[n], b1 = bias[n + 1];
#pragma unroll
        for (int mi = 0; mi < 2; mi++) {
            int m0 = bm + wm + mi * 16 + er;
            *(float2*)(C + (size_t)m0 * N + n) =
                make_float2(acc[mi][ni][0] + b0, acc[mi][ni][1] + b1);
            *(float2*)(C + (size_t)(m0 + 8) * N + n) =
                make_float2(acc[mi][ni][2] + b0, acc[mi][ni][3] + b1);
        }
    }
}

// ---------------------------------------------------------------------------
// Attention v4: warp per (sample, head); largest-n samples scheduled first.
// Writes bf16 hi/lo output planes (fuses out_proj input conversion).
// ---------------------------------------------------------------------------
__device__ __forceinline__ void store_bf_split(
    __nv_bfloat16* __restrict__ Oh, __nv_bfloat16* __restrict__ Ol,
    size_t base, const ull* ov, float linv)
{
    ull inv = pack2(linv, linv);
#pragma unroll
    for (int t = 0; t < 4; t++) {
        ull r0 = mul2(ov[2 * t], inv);
        ull r1 = mul2(ov[2 * t + 1], inv);
        float f0 = lo2(r0), f1 = hi2(r0), f2 = lo2(r1), f3 = hi2(r1);
        __nv_bfloat16 h0 = __float2bfloat16(f0), h1 = __float2bfloat16(f1),
                      h2 = __float2bfloat16(f2), h3 = __float2bfloat16(f3);
        ull hp = (ull)__bfloat16_as_ushort(h0) | ((ull)__bfloat16_as_ushort(h1) << 16)
               | ((ull)__bfloat16_as_ushort(h2) << 32) | ((ull)__bfloat16_as_ushort(h3) << 48);
        __nv_bfloat16 l0 = __float2bfloat16(f0 - __bfloat162float(h0));
        __nv_bfloat16 l1 = __float2bfloat16(f1 - __bfloat162float(h1));
        __nv_bfloat16 l2 = __float2bfloat16(f2 - __bfloat162float(h2));
        __nv_bfloat16 l3 = __float2bfloat16(f3 - __bfloat162float(h3));
        ull lp = (ull)__bfloat16_as_ushort(l0) | ((ull)__bfloat16_as_ushort(l1) << 16)
               | ((ull)__bfloat16_as_ushort(l2) << 32) | ((ull)__bfloat16_as_ushort(l3) << 48);
        *(ull*)(Oh + base + t * 4) = hp;
        *(ull*)(Ol + base + t * 4) = lp;
    }
}

__global__ __launch_bounds__(256) void attn_kernel(
    const float* __restrict__ Y,            // qkv [T][384]
    __nv_bfloat16* __restrict__ Oh,         // attn out hi plane [T][128]
    __nv_bfloat16* __restrict__ Ol,         // attn out lo plane [T][128]
    const int* __restrict__ agents, int B)
{
    extern __shared__ float smf[];       // 8 warps * (1024 K + 1024 V) floats
    // largest-first schedule (heuristic permutation; correctness reads agents[])
    int b = blockIdx.x;
    if (B == 2048) {
        int g = b >> 5, k = b & 31;
        b = (k << 6) + (63 - g);
    }
    const int tid  = threadIdx.x;
    const int w    = tid >> 5;           // head index
    const int lane = tid & 31;
    const int n    = agents[b];
    const int o    = g_offs[b];

    float* Ks = smf + w * 2048;
    float* Vs = Ks + 1024;

    int nseg = n * 4;
    for (int si = lane; si < nseg; si += 32) {
        int r = si >> 2, s = si & 3;
        const float* base = Y + (size_t)(o + r) * 384 + w * 16 + s * 4;
        *(float4*)(Ks + r * 16 + s * 4) = *(const float4*)(base + 128);
        *(float4*)(Vs + r * 16 + s * 4) = *(const float4*)(base + 256);
    }

    const int i0 = lane, i1 = lane + 32;
    const ull QSC = pack2(0.25f, 0.25f);

    ull q0[8];
#pragma unroll
    for (int d = 0; d < 8; d++) q0[d] = 0ull;
    if (i0 < n) {
        const float4* qp = (const float4*)(Y + (size_t)(o + i0) * 384 + w * 16);
#pragma unroll
        for (int t = 0; t < 4; t++) {
            float4 v = qp[t];
            q0[t * 2 + 0] = mul2(pack2(v.x, v.y), QSC);
            q0[t * 2 + 1] = mul2(pack2(v.z, v.w), QSC);
        }
    }

    if (n > 32) {
        ull q1[8];
#pragma unroll
        for (int d = 0; d < 8; d++) q1[d] = 0ull;
        if (i1 < n) {
            const float4* qp = (const float4*)(Y + (size_t)(o + i1) * 384 + w * 16);
#pragma unroll
            for (int t = 0; t < 4; t++) {
                float4 v = qp[t];
                q1[t * 2 + 0] = mul2(pack2(v.x, v.y), QSC);
                q1[t * 2 + 1] = mul2(pack2(v.z, v.w), QSC);
            }
        }
        __syncwarp();

        ull o0[8], o1[8];
#pragma unroll
        for (int d = 0; d < 8; d++) { o0[d] = 0ull; o1[d] = 0ull; }
        float l0 = 0.f, l1 = 0.f;

#pragma unroll 2
        for (int j = 0; j < n; j++) {
            const ulonglong2* kp = (const ulonglong2*)(Ks + j * 16);
            ulonglong2 k01 = kp[0], k23 = kp[1], k45 = kp[2], k67 = kp[3];
            ull kv[8] = {k01.x, k01.y, k23.x, k23.y, k45.x, k45.y, k67.x, k67.y};

            ull saA = 0, saB = 0, sbA = 0, sbB = 0;
#pragma unroll
            for (int d = 0; d < 4; d++) {
                saA = ffma2(q0[2 * d], kv[2 * d], saA);
                saB = ffma2(q0[2 * d + 1], kv[2 * d + 1], saB);
                sbA = ffma2(q1[2 * d], kv[2 * d], sbA);
                sbB = ffma2(q1[2 * d + 1], kv[2 * d + 1], sbB);
            }
            float e0 = __expf(hadd2(add2(saA, saB)));
            float e1 = __expf(hadd2(add2(sbA, sbB)));
            l0 += e0;
            l1 += e1;
            ull e00 = pack2(e0, e0);
            ull e11 = pack2(e1, e1);

            const ulonglong2* vp = (const ulonglong2*)(Vs + j * 16);
            ulonglong2 v01 = vp[0], v23 = vp[1], v45 = vp[2], v67 = vp[3];
            ull vv[8] = {v01.x, v01.y, v23.x, v23.y, v45.x, v45.y, v67.x, v67.y};
#pragma unroll
            for (int d = 0; d < 8; d++) {
                o0[d] = ffma2(e00, vv[d], o0[d]);
                o1[d] = ffma2(e11, vv[d], o1[d]);
            }
        }

        if (i0 < n) store_bf_split(Oh, Ol, (size_t)(o + i0) * 128 + w * 16, o0, 1.f / l0);
        if (i1 < n) store_bf_split(Oh, Ol, (size_t)(o + i1) * 128 + w * 16, o1, 1.f / l1);
    } else {
        __syncwarp();
        ull o0[8];
#pragma unroll
        for (int d = 0; d < 8; d++) o0[d] = 0ull;
        float l0 = 0.f;

#pragma unroll 2
        for (int j = 0; j < n; j++) {
            const ulonglong2* kp = (const ulonglong2*)(Ks + j * 16);
            ulonglong2 k01 = kp[0], k23 = kp[1], k45 = kp[2], k67 = kp[3];
            ull kv[8] = {k01.x, k01.y, k23.x, k23.y, k45.x, k45.y, k67.x, k67.y};

            ull saA = 0, saB = 0;
#pragma unroll
            for (int d = 0; d < 4; d++) {
                saA = ffma2(q0[2 * d], kv[2 * d], saA);
                saB = ffma2(q0[2 * d + 1], kv[2 * d + 1], saB);
            }
            float e0 = __expf(hadd2(add2(saA, saB)));
            l0 += e0;
            ull e00 = pack2(e0, e0);

            const ulonglong2* vp = (const ulonglong2*)(Vs + j * 16);
            ulonglong2 v01 = vp[0], v23 = vp[1], v45 = vp[2], v67 = vp[3];
            ull vv[8] = {v01.x, v01.y, v23.x, v23.y, v45.x, v45.y, v67.x, v67.y};
#pragma unroll
            for (int d = 0; d < 8; d++)
                o0[d] = ffma2(e00, vv[d], o0[d]);
        }

        if (i0 < n) store_bf_split(Oh, Ol, (size_t)(o + i0) * 128 + w * 16, o0, 1.f / l0);
    }
}

// ---------------------------------------------------------------------------
extern "C" void kernel_launch(void* const* d_in, const int* in_sizes, int n_in,
                              void* d_out, int out_size)
{
    const float* att_in = (const float*)d_in[0];
    const float* in_w   = (const float*)d_in[1];
    const float* in_b   = (const float*)d_in[2];
    const float* out_w  = (const float*)d_in[3];
    const float* out_b  = (const float*)d_in[4];
    const int*   agents = (const int*)d_in[5];

    const int T = in_sizes[0] / 128;
    const int B = in_sizes[5];
    float* out  = (float*)d_out;

    float *qkv = nullptr;
    __nv_bfloat16 *oh, *ol, *wh1, *wl1, *wh2, *wl2;
    cudaGetSymbolAddress((void**)&qkv, g_qkv);
    cudaGetSymbolAddress((void**)&oh,  g_oh);
    cudaGetSymbolAddress((void**)&ol,  g_ol);
    cudaGetSymbolAddress((void**)&wh1, g_wh1);
    cudaGetSymbolAddress((void**)&wl1, g_wl1);
    cudaGetSymbolAddress((void**)&wh2, g_wh2);
    cudaGetSymbolAddress((void**)&wl2, g_wl2);

    cudaFuncSetAttribute(gemm_tc_kernel<true>,  cudaFuncAttributeMaxDynamicSharedMemorySize, GEMM_SMEM);
    cudaFuncSetAttribute(gemm_tc_kernel<false>, cudaFuncAttributeMaxDynamicSharedMemorySize, GEMM_SMEM);
    cudaFuncSetAttribute(attn_kernel, cudaFuncAttributeMaxDynamicSharedMemorySize, 65536);

    convw_kernel<<<64, 256>>>(in_w, out_w);
    scan_kernel<<<1, 256>>>(agents, B);

    // QKV GEMM: [T x 384], A converted in-kernel
    dim3 g1(T / 64, 3);
    gemm_tc_kernel<true><<<g1, 256, GEMM_SMEM>>>(att_in, nullptr, nullptr,
                                                 wh1, wl1, in_b, qkv, 384);

    // attention -> bf16 hi/lo planes
    attn_kernel<<<B, 256, 65536>>>(qkv, oh, ol, agents, B);

    // out_proj GEMM: [T x 128], A = preconverted planes
    dim3 g2(T / 64, 1);
    gemm_tc_kernel<false><<<g2, 256, GEMM_SMEM>>>(nullptr, oh, ol,
                                                  wh2, wl2, out_b, out, 128);
}